// round 15
// baseline (speedup 1.0000x reference)
#include <cuda_runtime.h>
#include <cuda_fp16.h>
#include <math.h>
#include <cstdint>

// Problem constants
namespace {
constexpr int B = 4, T = 2048, C = 1024, H = 16, D = 64, R = 32;
constexpr int M = B * T;   // 8192
constexpr int K = C;       // 1024
}

// Scratch (device globals — no allocation allowed)
__device__ __half g_xhi[M * C], g_xlo[M * C];
__device__ __half g_whi[4 * C * C];                  // Wq,Wk,Wv,Wo (hi only)
__device__ __half g_ohi[M * C], g_olo[M * C];
__device__ __half g_qhi[B * H * T * D], g_qlo[B * H * T * D];
__device__ __half g_khi[B * H * T * D];              // hi only (B-side)
__device__ __half g_vhi[B * H * T * D];              // hi only (B-side)
// Mask compaction: indices of unmasked keys per batch + counts
__device__ int g_cidx[B * T];
__device__ int g_cnt[B];

// ---------------------------------------------------------------------------
// Helpers
// ---------------------------------------------------------------------------
__device__ __forceinline__ uint32_t smem_u32(const void* p) {
    uint32_t a;
    asm("{ .reg .u64 t; cvta.to.shared.u64 t, %1; cvt.u32.u64 %0, t; }"
        : "=r"(a) : "l"(p));
    return a;
}

__device__ __forceinline__ void ldsm_x4(uint32_t* r, uint32_t addr) {
    asm volatile("ldmatrix.sync.aligned.m8n8.x4.shared.b16 {%0,%1,%2,%3}, [%4];"
                 : "=r"(r[0]), "=r"(r[1]), "=r"(r[2]), "=r"(r[3]) : "r"(addr));
}
__device__ __forceinline__ void ldsm_x4_t(uint32_t* r, uint32_t addr) {
    asm volatile("ldmatrix.sync.aligned.m8n8.x4.trans.shared.b16 {%0,%1,%2,%3}, [%4];"
                 : "=r"(r[0]), "=r"(r[1]), "=r"(r[2]), "=r"(r[3]) : "r"(addr));
}

__device__ __forceinline__ void mma_f16(float* c, const uint32_t* a,
                                        uint32_t b0, uint32_t b1) {
    asm volatile(
        "mma.sync.aligned.m16n8k16.row.col.f32.f16.f16.f32 "
        "{%0,%1,%2,%3}, {%4,%5,%6,%7}, {%8,%9}, {%0,%1,%2,%3};"
        : "+f"(c[0]), "+f"(c[1]), "+f"(c[2]), "+f"(c[3])
        : "r"(a[0]), "r"(a[1]), "r"(a[2]), "r"(a[3]), "r"(b0), "r"(b1));
}

__device__ __forceinline__ uint32_t packh(float a, float b) {
    __half2 t = __floats2half2_rn(a, b);
    return *reinterpret_cast<uint32_t*>(&t);
}
__device__ __forceinline__ uint32_t pack_resh(float a, float b, uint32_t hp) {
    __half2 hv = *reinterpret_cast<__half2*>(&hp);
    return packh(a - __half2float(hv.x), b - __half2float(hv.y));
}

// --- bulk copy + mbarrier (sm_90 base features) ---
__device__ __forceinline__ void cp_bulk(uint32_t dst, const void* src,
                                        uint32_t bytes, uint32_t mbar) {
    asm volatile(
        "cp.async.bulk.shared::cluster.global.mbarrier::complete_tx::bytes "
        "[%0], [%1], %2, [%3];"
        :: "r"(dst), "l"(src), "r"(bytes), "r"(mbar) : "memory");
}
__device__ __forceinline__ void mbar_init(uint32_t addr, uint32_t cnt) {
    asm volatile("mbarrier.init.shared.b64 [%0], %1;" :: "r"(addr), "r"(cnt) : "memory");
}
__device__ __forceinline__ void mbar_expect(uint32_t addr, uint32_t bytes) {
    asm volatile("mbarrier.arrive.expect_tx.shared.b64 _, [%0], %1;"
                 :: "r"(addr), "r"(bytes) : "memory");
}
__device__ __forceinline__ void mbar_arrive(uint32_t addr) {
    asm volatile("mbarrier.arrive.shared.b64 _, [%0];" :: "r"(addr) : "memory");
}
__device__ __forceinline__ void mbar_wait(uint32_t addr, uint32_t parity) {
    asm volatile(
        "{\n\t.reg .pred P;\n\t"
        "WL_%=:\n\t"
        "mbarrier.try_wait.parity.acquire.cta.shared::cta.b64 P, [%0], %1, 0x989680;\n\t"
        "@P bra.uni WD_%=;\n\t"
        "bra.uni WL_%=;\n\t"
        "WD_%=:\n\t}"
        :: "r"(addr), "r"(parity) : "memory");
}

// ---------------------------------------------------------------------------
// Mask compaction: per batch, list of unmasked key indices + count.
// One block per batch, 256 threads, 8 elems/thread, Hillis-Steele scan.
// ---------------------------------------------------------------------------
__global__ void compact_mask(const int* __restrict__ mask) {
    const int b = blockIdx.x;
    const int tid = threadIdx.x;
    __shared__ int ssum[256];
    int loc[8];
    int cnt = 0;
    const int base = b * T + tid * 8;
    int mv[8];
    #pragma unroll
    for (int i = 0; i < 8; i++) {
        mv[i] = mask[base + i];
        loc[i] = cnt;
        cnt += (mv[i] != 0);
    }
    ssum[tid] = cnt;
    __syncthreads();
    for (int off = 1; off < 256; off <<= 1) {
        int v = (tid >= off) ? ssum[tid - off] : 0;
        __syncthreads();
        ssum[tid] += v;
        __syncthreads();
    }
    const int pre = (tid == 0) ? 0 : ssum[tid - 1];
    #pragma unroll
    for (int i = 0; i < 8; i++) {
        if (mv[i] != 0)
            g_cidx[b * T + pre + loc[i]] = tid * 8 + i;
    }
    if (tid == 255) g_cnt[b] = ssum[255];
}

// ---------------------------------------------------------------------------
// Merged split: fp32 -> fp16 hi(/lo) into blocked-swizzled layout.
// ---------------------------------------------------------------------------
__global__ void split_all(const float* __restrict__ x,
                          const float* __restrict__ Wq,
                          const float* __restrict__ Wk,
                          const float* __restrict__ Wv,
                          const float* __restrict__ Wo) {
    const int bx = blockIdx.x;
    const float* src;
    __half *hi, *lo = nullptr;
    int rows, base;
    bool wantLo;
    if (bx < 4096) {
        src = x; hi = g_xhi; lo = g_xlo; rows = M; base = 0; wantLo = true;
    } else {
        const int j = (bx - 4096) >> 9;
        base = 4096 + (j << 9);
        src = (j == 0) ? Wq : (j == 1) ? Wk : (j == 2) ? Wv : Wo;
        hi = g_whi + (size_t)j * C * C;
        rows = C; wantLo = false;
    }
    const int idx = (bx - base) * 256 + threadIdx.x;
    const int m  = idx >> 7;
    const int kc = idx & 127;
    const float4* p = reinterpret_cast<const float4*>(src + (size_t)m * 1024 + kc * 8);
    float4 a = p[0], b = p[1];
    uint32_t h[4], l[4];
    h[0] = packh(a.x, a.y); l[0] = pack_resh(a.x, a.y, h[0]);
    h[1] = packh(a.z, a.w); l[1] = pack_resh(a.z, a.w, h[1]);
    h[2] = packh(b.x, b.y); l[2] = pack_resh(b.x, b.y, h[2]);
    h[3] = packh(b.z, b.w); l[3] = pack_resh(b.z, b.w, h[3]);
    const int kt = kc >> 2, cin = kc & 3;
    const int swz = cin ^ ((m >> 1) & 3);
    const size_t off = ((size_t)kt * rows + m) * 32 + swz * 8;
    *reinterpret_cast<uint4*>(hi + off) = make_uint4(h[0], h[1], h[2], h[3]);
    if (wantLo)
        *reinterpret_cast<uint4*>(lo + off) = make_uint4(l[0], l[1], l[2], l[3]);
}

// ---------------------------------------------------------------------------
// cp.async.bulk 4-stage, fp16 2-pass GEMM (round-14, unchanged).
// ---------------------------------------------------------------------------
constexpr int AT_B = 128 * 64;
constexpr int STG  = 3 * AT_B;
constexpr int NST  = 4;
constexpr int GEMM_SMEM = NST * STG + 64;

template <int MODE>
__global__ __launch_bounds__(256, 2) void tc_gemm(
    const float* __restrict__ b0_, const float* __restrict__ b1_,
    const float* __restrict__ b2_, const float* __restrict__ rope,
    float* __restrict__ out_ptr)
{
    extern __shared__ __align__(16) char dynsmem[];

    const int tid  = threadIdx.x;
    const int lane = tid & 31;
    const int wid  = tid >> 5;
    const int wm   = wid & 1;
    const int wn   = wid >> 1;
    const int m0   = blockIdx.y * 128;
    const int n0   = blockIdx.x * 128;

    const __half *Ahi, *Alo, *Bh;
    const float* bias;
    if (MODE == 0) {
        const int z = blockIdx.z;
        Ahi = g_xhi; Alo = g_xlo;
        Bh = g_whi + (size_t)z * C * C;
        bias = (z == 0) ? b0_ : (z == 1) ? b1_ : b2_;
    } else {
        Ahi = g_ohi; Alo = g_olo;
        Bh = g_whi + (size_t)3 * C * C;
        bias = b0_;
    }

    const uint32_t sbase = smem_u32(dynsmem);
    const uint32_t fullb = sbase + NST * STG;
    const uint32_t emptb = fullb + NST * 8;

    if (tid == 0) {
        #pragma unroll
        for (int s = 0; s < NST; s++) {
            mbar_init(fullb + s * 8, 1);
            mbar_init(emptb + s * 8, 8);
        }
    }
    __syncthreads();

    auto issue = [&](int kt) {
        const int s = kt & 3;
        const uint32_t sb = sbase + s * STG;
        const uint32_t mb = fullb + s * 8;
        mbar_expect(mb, STG);
        cp_bulk(sb,             Ahi + ((size_t)kt * M + m0) * 32, AT_B, mb);
        cp_bulk(sb + AT_B,      Alo + ((size_t)kt * M + m0) * 32, AT_B, mb);
        cp_bulk(sb + 2 * AT_B,  Bh  + ((size_t)kt * C + n0) * 32, AT_B, mb);
    };

    if (tid == 0) { issue(0); issue(1); issue(2); issue(3); }

    float acc[4][4][4];
    #pragma unroll
    for (int i = 0; i < 4; i++)
        #pragma unroll
        for (int j = 0; j < 4; j++)
            #pragma unroll
            for (int e = 0; e < 4; e++) acc[i][j][e] = 0.f;

    const int fr = (lane & 7) + ((lane >> 3) & 1) * 8;
    const int ch = (lane >> 4) & 1;
    const int raB = wm * 64 + fr;
    const int rbB = wn * 32 + fr;

    auto compute_ktile = [&](uint32_t st) {
        #pragma unroll
        for (int kf = 0; kf < 2; kf++) {
            const int c0 = kf * 2 + ch;
            uint32_t ah[4][4], bh[2][4];
            #pragma unroll
            for (int fm = 0; fm < 4; fm++) {
                const int ra = raB + fm * 16;
                ldsm_x4(ah[fm], st + ra * 64 + ((c0 ^ ((ra >> 1) & 3)) << 4));
            }
            #pragma unroll
            for (int f2 = 0; f2 < 2; f2++) {
                const int rb = rbB + f2 * 16;
                ldsm_x4(bh[f2], st + 2 * AT_B + rb * 64 + ((c0 ^ ((rb >> 1) & 3)) << 4));
            }
            #pragma unroll
            for (int fm = 0; fm < 4; fm++)
                #pragma unroll
                for (int fn = 0; fn < 4; fn++)
                    mma_f16(acc[fm][fn], ah[fm],
                            bh[fn >> 1][fn & 1], bh[fn >> 1][2 + (fn & 1)]);
            {
                uint32_t al[4][4];
                #pragma unroll
                for (int fm = 0; fm < 4; fm++) {
                    const int ra = raB + fm * 16;
                    ldsm_x4(al[fm], st + AT_B + ra * 64 + ((c0 ^ ((ra >> 1) & 3)) << 4));
                }
                #pragma unroll
                for (int fm = 0; fm < 4; fm++)
                    #pragma unroll
                    for (int fn = 0; fn < 4; fn++)
                        mma_f16(acc[fm][fn], al[fm],
                                bh[fn >> 1][fn & 1], bh[fn >> 1][2 + (fn & 1)]);
            }
        }
    };

    constexpr int NKT = K / 32;
    for (int kt = 0; kt < NKT; kt++) {
        const int s = kt & 3;
        const int p = (kt >> 2) & 1;
        mbar_wait(fullb + s * 8, p);
        compute_ktile(sbase + s * STG);
        __syncwarp();
        if (lane == 0) mbar_arrive(emptb + s * 8);
        if (wid == 0 && kt + NST < NKT) {
            mbar_wait(emptb + s * 8, p);
            if (lane == 0) issue(kt + NST);
        }
    }

    // ------------------- Epilogue -------------------
    const int gid = lane >> 2, tig = lane & 3;

    if (MODE == 0) {
        const int z = blockIdx.z;
        __half* dhi = (z == 0) ? g_qhi : (z == 1) ? g_khi : g_vhi;
        const float scale = (z == 0) ? 0.125f : 1.f;
        const bool doRope = (z < 2) && ((wn & 1) == 0);
        const int hh = (n0 >> 6) + (wn >> 1);

        #pragma unroll
        for (int fm = 0; fm < 4; fm++) {
            #pragma unroll
            for (int hf = 0; hf < 2; hf++) {
                const int m  = m0 + wm * 64 + fm * 16 + gid + hf * 8;
                const int bb = m >> 11, tt = m & (T - 1);
                float2 val[4];
                #pragma unroll
                for (int fn = 0; fn < 4; fn++) {
                    const int n = n0 + wn * 32 + fn * 8 + tig * 2;
                    val[fn].x = acc[fm][fn][hf * 2 + 0] + bias[n];
                    val[fn].y = acc[fm][fn][hf * 2 + 1] + bias[n + 1];
                }
                if (doRope) {
                    #pragma unroll
                    for (int fn = 0; fn < 2; fn++) {
                        const int i = fn * 8 + tig * 2;
                        const float2 c = *reinterpret_cast<const float2*>(rope + tt * R + i);
                        const float2 s = *reinterpret_cast<const float2*>(rope + T * R + tt * R + i);
                        const float2 x1 = val[fn], x2 = val[fn + 2];
                        val[fn].x     = x1.x * c.x - x2.x * s.x;
                        val[fn].y     = x1.y * c.y - x2.y * s.y;
                        val[fn + 2].x = x2.x * c.x + x1.x * s.x;
                        val[fn + 2].y = x2.y * c.y + x1.y * s.y;
                    }
                }
                #pragma unroll
                for (int fn = 0; fn < 4; fn++) {
                    const int d = (wn & 1) * 32 + fn * 8 + tig * 2;
                    const float v0 = val[fn].x * scale, v1 = val[fn].y * scale;
                    uint32_t hv = packh(v0, v1);
                    const size_t off = (((size_t)bb * H + hh) * T + tt) * D + d;
                    *reinterpret_cast<uint32_t*>(dhi + off) = hv;
                    if (z == 0) {
                        uint32_t lv = pack_resh(v0, v1, hv);
                        *reinterpret_cast<uint32_t*>(g_qlo + off) = lv;
                    }
                }
            }
        }
    } else {
        #pragma unroll
        for (int fm = 0; fm < 4; fm++) {
            const int mlo = m0 + wm * 64 + fm * 16 + gid;
            #pragma unroll
            for (int fn = 0; fn < 4; fn++) {
                const int n = n0 + wn * 32 + fn * 8 + tig * 2;
                const float bv0 = bias[n], bv1 = bias[n + 1];
                #pragma unroll
                for (int hf = 0; hf < 2; hf++) {
                    const int m = mlo + hf * 8;
                    float* p = out_ptr + (size_t)m * C + n;
                    p[0] = acc[fm][fn][hf * 2 + 0] + bv0;
                    p[1] = acc[fm][fn][hf * 2 + 1] + bv1;
                }
            }
        }
    }
}

// ---------------------------------------------------------------------------
// Tensor-core flash attention, fp16 2-pass, chunked, MASK-COMPACTED keys.
// Only unmasked keys (gathered via g_cidx) are processed: exact transform,
// ~halves the kv loop.
// ---------------------------------------------------------------------------
constexpr int AST    = 72;
constexpr int KVTILE = 64 * AST * 2;
constexpr int KVST   = 2 * KVTILE;
constexpr int ATT_SMEM = 2 * 128 * AST * 2 + 2 * KVST + 2 * 64 * 4;

__global__ __launch_bounds__(256, 2) void attn_tc(const int* __restrict__ mask)
{
    extern __shared__ __align__(16) char asmem[];
    __half* Qh = reinterpret_cast<__half*>(asmem);
    __half* Ql = Qh + 128 * AST;
    char* KVbase = asmem + 2 * 128 * AST * 2;
    float* msks = reinterpret_cast<float*>(KVbase + 2 * KVST);

    const int tid  = threadIdx.x;
    const int lane = tid & 31, wid = tid >> 5;
    const int gid  = lane >> 2, tig = lane & 3;
    const int bh = blockIdx.y, b = bh >> 4, h = bh & 15;
    const int q0 = blockIdx.x * 128;

    const int cnt = g_cnt[b];
    const int nsteps = (cnt + 63) >> 6;
    const int* cidx = g_cidx + b * T;

    const size_t qgbase = ((size_t)bh * T + q0) * 64;
    #pragma unroll
    for (int i = 0; i < 4; i++) {
        const int idx = tid + i * 256;
        const int row = idx >> 3, c8 = (idx & 7) * 8;
        *reinterpret_cast<float4*>(reinterpret_cast<char*>(Qh) + row * 144 + c8 * 2) =
            *reinterpret_cast<const float4*>(g_qhi + qgbase + row * 64 + c8);
        *reinterpret_cast<float4*>(reinterpret_cast<char*>(Ql) + row * 144 + c8 * 2) =
            *reinterpret_cast<const float4*>(g_qlo + qgbase + row * 64 + c8);
    }

    float4 st[4];
    const size_t kvgrow = (size_t)bh * T;
    auto ldkv = [&](int kv0) {
        #pragma unroll
        for (int i = 0; i < 4; i++) {
            const int t_ = i >> 1;
            const int idx = tid + (i & 1) * 256;
            const int row = idx >> 3, c8 = (idx & 7) * 8;
            const int kr = kv0 + row;
            const int gr = (kr < cnt) ? cidx[kr] : 0;
            const __half* src = (t_ == 0) ? g_khi : g_vhi;
            st[i] = *reinterpret_cast<const float4*>(src + (kvgrow + gr) * 64 + c8);
        }
    };
    auto stkv = [&](int stage, int kv0) {
        char* sb = KVbase + stage * KVST;
        #pragma unroll
        for (int i = 0; i < 4; i++) {
            const int t_ = i >> 1;
            const int idx = tid + (i & 1) * 256;
            const int row = idx >> 3, c8 = (idx & 7) * 8;
            *reinterpret_cast<float4*>(sb + t_ * KVTILE + row * 144 + c8 * 2) = st[i];
        }
        if (tid < 64) msks[stage * 64 + tid] = (kv0 + tid < cnt) ? 0.f : -1e30f;
    };

    ldkv(0);
    __syncthreads();
    stkv(0, 0);
    __syncthreads();

    uint32_t qh[4][4], ql[4][4];
    {
        const uint32_t qhb = smem_u32(Qh), qlb = smem_u32(Ql);
        const int qr = wid * 16 + (lane & 15);
        const int qc = (lane >> 4) * 16;
        #pragma unroll
        for (int kc = 0; kc < 4; kc++) {
            ldsm_x4(qh[kc], qhb + qr * 144 + kc * 32 + qc);
            ldsm_x4(ql[kc], qlb + qr * 144 + kc * 32 + qc);
        }
    }

    float of[8][4];
    #pragma unroll
    for (int i = 0; i < 8; i++)
        #pragma unroll
        for (int e = 0; e < 4; e++) of[i][e] = 0.f;
    float li0 = 0.f, li1 = 0.f;

    const uint32_t kvb0 = smem_u32(KVbase);
    const int lr = lane & 15;
    const int lc = (lane >> 4) * 16;

    for (int kt = 0; kt < nsteps; kt++) {
        if (kt + 1 < nsteps) ldkv((kt + 1) * 64);

        const int s = kt & 1;
        const uint32_t khb = kvb0 + s * KVST;
        const uint32_t vhb = khb + KVTILE;

        #pragma unroll
        for (int chunk = 0; chunk < 2; chunk++) {
            float sf[4][4];
            #pragma unroll
            for (int i = 0; i < 4; i++)
                #pragma unroll
                for (int e = 0; e < 4; e++) sf[i][e] = 0.f;

            #pragma unroll
            for (int kc = 0; kc < 4; kc++) {
                #pragma unroll
                for (int ng = 0; ng < 2; ng++) {
                    uint32_t kb[4];
                    const uint32_t a = (chunk * 32 + ng * 16 + lr) * 144 + kc * 32 + lc;
                    ldsm_x4(kb, khb + a);
                    mma_f16(sf[2 * ng],     qh[kc], kb[0], kb[2]);
                    mma_f16(sf[2 * ng],     ql[kc], kb[0], kb[2]);
                    mma_f16(sf[2 * ng + 1], qh[kc], kb[1], kb[3]);
                    mma_f16(sf[2 * ng + 1], ql[kc], kb[1], kb[3]);
                }
            }

            float r0 = 0.f, r1 = 0.f;
            #pragma unroll
            for (int nf = 0; nf < 4; nf++) {
                const float m0 = msks[s * 64 + chunk * 32 + nf * 8 + tig * 2];
                const float m1 = msks[s * 64 + chunk * 32 + nf * 8 + tig * 2 + 1];
                const float e0 = __expf(sf[nf][0] + m0);
                const float e1 = __expf(sf[nf][1] + m1);
                const float e2 = __expf(sf[nf][2] + m0);
                const float e3 = __expf(sf[nf][3] + m1);
                sf[nf][0] = e0; sf[nf][1] = e1; sf[nf][2] = e2; sf[nf][3] = e3;
                r0 += e0 + e1; r1 += e2 + e3;
            }
            r0 += __shfl_xor_sync(0xffffffffu, r0, 1);
            r0 += __shfl_xor_sync(0xffffffffu, r0, 2);
            r1 += __shfl_xor_sync(0xffffffffu, r1, 1);
            r1 += __shfl_xor_sync(0xffffffffu, r1, 2);
            li0 += r0; li1 += r1;

            uint32_t ah[2][4], al[2][4];
            #pragma unroll
            for (int kc2 = 0; kc2 < 2; kc2++) {
                const float* eA = sf[2 * kc2];
                const float* eB = sf[2 * kc2 + 1];
                ah[kc2][0] = packh(eA[0], eA[1]);
                ah[kc2][1] = packh(eA[2], eA[3]);
                ah[kc2][2] = packh(eB[0], eB[1]);
                ah[kc2][3] = packh(eB[2], eB[3]);
                al[kc2][0] = pack_resh(eA[0], eA[1], ah[kc2][0]);
                al[kc2][1] = pack_resh(eA[2], eA[3], ah[kc2][1]);
                al[kc2][2] = pack_resh(eB[0], eB[1], ah[kc2][2]);
                al[kc2][3] = pack_resh(eB[2], eB[3], ah[kc2][3]);
            }

            #pragma unroll
            for (int kc2 = 0; kc2 < 2; kc2++) {
                #pragma unroll
                for (int dg = 0; dg < 4; dg++) {
                    uint32_t vb[4];
                    const uint32_t a = (chunk * 32 + kc2 * 16 + lr) * 144 + dg * 32 + lc;
                    ldsm_x4_t(vb, vhb + a);
                    mma_f16(of[2 * dg],     ah[kc2], vb[0], vb[1]);
                    mma_f16(of[2 * dg],     al[kc2], vb[0], vb[1]);
                    mma_f16(of[2 * dg + 1], ah[kc2], vb[2], vb[3]);
                    mma_f16(of[2 * dg + 1], al[kc2], vb[2], vb[3]);
                }
            }
        }

        if (kt + 1 < nsteps) stkv((kt + 1) & 1, (kt + 1) * 64);
        __syncthreads();
    }

    // normalize + split to fp16 hi/lo, write blocked-swizzled [ktile][m][32]
    const float i0 = 1.f / li0, i1 = 1.f / li1;
    const int r0w = q0 + wid * 16 + gid;
    const int r1w = r0w + 8;
    const int ma = b * T + r0w, mb = b * T + r1w;
    #pragma unroll
    for (int df = 0; df < 8; df++) {
        const int c   = h * 64 + df * 8 + tig * 2;
        const int ktc = c >> 5, cin = (c >> 3) & 3, el = c & 7;
        const size_t oa = ((size_t)ktc * M + ma) * 32 + ((cin ^ ((ma >> 1) & 3)) << 3) + el;
        const size_t ob = ((size_t)ktc * M + mb) * 32 + ((cin ^ ((mb >> 1) & 3)) << 3) + el;
        const float v0 = of[df][0] * i0, v1 = of[df][1] * i0;
        const float v2 = of[df][2] * i1, v3 = of[df][3] * i1;
        uint32_t h0 = packh(v0, v1);
        uint32_t l0 = pack_resh(v0, v1, h0);
        uint32_t h1 = packh(v2, v3);
        uint32_t l1 = pack_resh(v2, v3, h1);
        *reinterpret_cast<uint32_t*>(g_ohi + oa) = h0;
        *reinterpret_cast<uint32_t*>(g_olo + oa) = l0;
        *reinterpret_cast<uint32_t*>(g_ohi + ob) = h1;
        *reinterpret_cast<uint32_t*>(g_olo + ob) = l1;
    }
}

// ---------------------------------------------------------------------------
extern "C" void kernel_launch(void* const* d_in, const int* in_sizes, int n_in,
                              void* d_out, int out_size)
{
    const float* x    = (const float*)d_in[0];
    const float* rope = (const float*)d_in[1];
    const int*   mask = (const int*)  d_in[2];
    const float* Wq = (const float*)d_in[3];
    const float* bq = (const float*)d_in[4];
    const float* bk = (const float*)d_in[6];
    const float* Wk = (const float*)d_in[5];
    const float* Wv = (const float*)d_in[7];
    const float* bv = (const float*)d_in[8];
    const float* Wo = (const float*)d_in[9];
    const float* bo = (const float*)d_in[10];
    float* out = (float*)d_out;

    // Mask compaction (tiny) + merged split
    compact_mask<<<B, 256>>>(mask);
    split_all<<<4096 + 4 * 512, 256>>>(x, Wq, Wk, Wv, Wo);

    // QKV projections
    cudaFuncSetAttribute(tc_gemm<0>, cudaFuncAttributeMaxDynamicSharedMemorySize, GEMM_SMEM);
    cudaFuncSetAttribute(tc_gemm<1>, cudaFuncAttributeMaxDynamicSharedMemorySize, GEMM_SMEM);
    tc_gemm<0><<<dim3(C / 128, M / 128, 3), 256, GEMM_SMEM>>>(bq, bk, bv, rope, nullptr);

    // Tensor-core attention over compacted keys
    cudaFuncSetAttribute(attn_tc, cudaFuncAttributeMaxDynamicSharedMemorySize, ATT_SMEM);
    attn_tc<<<dim3(T / 128, B * H), 256, ATT_SMEM>>>(mask);

    // Output projection
    tc_gemm<1><<<dim3(C / 128, M / 128, 1), 256, GEMM_SMEM>>>(bo, nullptr, nullptr, nullptr, out);
}

// round 16
// speedup vs baseline: 1.5527x; 1.5527x over previous
#include <cuda_runtime.h>
#include <cuda_fp16.h>
#include <math.h>
#include <cstdint>

// Problem constants
namespace {
constexpr int B = 4, T = 2048, C = 1024, H = 16, D = 64, R = 32;
constexpr int M = B * T;   // 8192
constexpr int K = C;       // 1024
}

// Scratch (device globals — no allocation allowed)
__device__ __half g_xhi[M * C], g_xlo[M * C];
__device__ __half g_whi[4 * C * C];                  // Wq,Wk,Wv,Wo (hi only)
__device__ __half g_ohi[M * C], g_olo[M * C];
__device__ __half g_qhi[B * H * T * D], g_qlo[B * H * T * D];
__device__ __half g_khi[B * H * T * D];              // hi only, COMPACTED rows
__device__ __half g_vhi[B * H * T * D];              // hi only, COMPACTED rows
// Mask compaction: compact position per original row (-1 if masked) + counts
__device__ int g_cpos[B * T];
__device__ int g_cnt[B];

// ---------------------------------------------------------------------------
// Helpers
// ---------------------------------------------------------------------------
__device__ __forceinline__ uint32_t smem_u32(const void* p) {
    uint32_t a;
    asm("{ .reg .u64 t; cvta.to.shared.u64 t, %1; cvt.u32.u64 %0, t; }"
        : "=r"(a) : "l"(p));
    return a;
}

__device__ __forceinline__ void ldsm_x4(uint32_t* r, uint32_t addr) {
    asm volatile("ldmatrix.sync.aligned.m8n8.x4.shared.b16 {%0,%1,%2,%3}, [%4];"
                 : "=r"(r[0]), "=r"(r[1]), "=r"(r[2]), "=r"(r[3]) : "r"(addr));
}
__device__ __forceinline__ void ldsm_x4_t(uint32_t* r, uint32_t addr) {
    asm volatile("ldmatrix.sync.aligned.m8n8.x4.trans.shared.b16 {%0,%1,%2,%3}, [%4];"
                 : "=r"(r[0]), "=r"(r[1]), "=r"(r[2]), "=r"(r[3]) : "r"(addr));
}

__device__ __forceinline__ void mma_f16(float* c, const uint32_t* a,
                                        uint32_t b0, uint32_t b1) {
    asm volatile(
        "mma.sync.aligned.m16n8k16.row.col.f32.f16.f16.f32 "
        "{%0,%1,%2,%3}, {%4,%5,%6,%7}, {%8,%9}, {%0,%1,%2,%3};"
        : "+f"(c[0]), "+f"(c[1]), "+f"(c[2]), "+f"(c[3])
        : "r"(a[0]), "r"(a[1]), "r"(a[2]), "r"(a[3]), "r"(b0), "r"(b1));
}

__device__ __forceinline__ uint32_t packh(float a, float b) {
    __half2 t = __floats2half2_rn(a, b);
    return *reinterpret_cast<uint32_t*>(&t);
}
__device__ __forceinline__ uint32_t pack_resh(float a, float b, uint32_t hp) {
    __half2 hv = *reinterpret_cast<__half2*>(&hp);
    return packh(a - __half2float(hv.x), b - __half2float(hv.y));
}

// --- bulk copy + mbarrier (sm_90 base features) ---
__device__ __forceinline__ void cp_bulk(uint32_t dst, const void* src,
                                        uint32_t bytes, uint32_t mbar) {
    asm volatile(
        "cp.async.bulk.shared::cluster.global.mbarrier::complete_tx::bytes "
        "[%0], [%1], %2, [%3];"
        :: "r"(dst), "l"(src), "r"(bytes), "r"(mbar) : "memory");
}
__device__ __forceinline__ void mbar_init(uint32_t addr, uint32_t cnt) {
    asm volatile("mbarrier.init.shared.b64 [%0], %1;" :: "r"(addr), "r"(cnt) : "memory");
}
__device__ __forceinline__ void mbar_expect(uint32_t addr, uint32_t bytes) {
    asm volatile("mbarrier.arrive.expect_tx.shared.b64 _, [%0], %1;"
                 :: "r"(addr), "r"(bytes) : "memory");
}
__device__ __forceinline__ void mbar_arrive(uint32_t addr) {
    asm volatile("mbarrier.arrive.shared.b64 _, [%0];" :: "r"(addr) : "memory");
}
__device__ __forceinline__ void mbar_wait(uint32_t addr, uint32_t parity) {
    asm volatile(
        "{\n\t.reg .pred P;\n\t"
        "WL_%=:\n\t"
        "mbarrier.try_wait.parity.acquire.cta.shared::cta.b64 P, [%0], %1, 0x989680;\n\t"
        "@P bra.uni WD_%=;\n\t"
        "bra.uni WL_%=;\n\t"
        "WD_%=:\n\t}"
        :: "r"(addr), "r"(parity) : "memory");
}

// ---------------------------------------------------------------------------
// Mask compaction: per batch, compact position of each row (-1 if masked).
// One block per batch, 256 threads, 8 elems/thread, Hillis-Steele scan.
// ---------------------------------------------------------------------------
__global__ void compact_mask(const int* __restrict__ mask) {
    const int b = blockIdx.x;
    const int tid = threadIdx.x;
    __shared__ int ssum[256];
    int loc[8];
    int cnt = 0;
    const int base = b * T + tid * 8;
    int mv[8];
    #pragma unroll
    for (int i = 0; i < 8; i++) {
        mv[i] = mask[base + i];
        loc[i] = cnt;
        cnt += (mv[i] != 0);
    }
    ssum[tid] = cnt;
    __syncthreads();
    for (int off = 1; off < 256; off <<= 1) {
        int v = (tid >= off) ? ssum[tid - off] : 0;
        __syncthreads();
        ssum[tid] += v;
        __syncthreads();
    }
    const int pre = (tid == 0) ? 0 : ssum[tid - 1];
    #pragma unroll
    for (int i = 0; i < 8; i++)
        g_cpos[base + i] = mv[i] ? (pre + loc[i]) : -1;
    if (tid == 255) g_cnt[b] = ssum[255];
}

// ---------------------------------------------------------------------------
// Merged split: fp32 -> fp16 hi(/lo) into blocked-swizzled layout.
// ---------------------------------------------------------------------------
__global__ void split_all(const float* __restrict__ x,
                          const float* __restrict__ Wq,
                          const float* __restrict__ Wk,
                          const float* __restrict__ Wv,
                          const float* __restrict__ Wo) {
    const int bx = blockIdx.x;
    const float* src;
    __half *hi, *lo = nullptr;
    int rows, base;
    bool wantLo;
    if (bx < 4096) {
        src = x; hi = g_xhi; lo = g_xlo; rows = M; base = 0; wantLo = true;
    } else {
        const int j = (bx - 4096) >> 9;
        base = 4096 + (j << 9);
        src = (j == 0) ? Wq : (j == 1) ? Wk : (j == 2) ? Wv : Wo;
        hi = g_whi + (size_t)j * C * C;
        rows = C; wantLo = false;
    }
    const int idx = (bx - base) * 256 + threadIdx.x;
    const int m  = idx >> 7;
    const int kc = idx & 127;
    const float4* p = reinterpret_cast<const float4*>(src + (size_t)m * 1024 + kc * 8);
    float4 a = p[0], b = p[1];
    uint32_t h[4], l[4];
    h[0] = packh(a.x, a.y); l[0] = pack_resh(a.x, a.y, h[0]);
    h[1] = packh(a.z, a.w); l[1] = pack_resh(a.z, a.w, h[1]);
    h[2] = packh(b.x, b.y); l[2] = pack_resh(b.x, b.y, h[2]);
    h[3] = packh(b.z, b.w); l[3] = pack_resh(b.z, b.w, h[3]);
    const int kt = kc >> 2, cin = kc & 3;
    const int swz = cin ^ ((m >> 1) & 3);
    const size_t off = ((size_t)kt * rows + m) * 32 + swz * 8;
    *reinterpret_cast<uint4*>(hi + off) = make_uint4(h[0], h[1], h[2], h[3]);
    if (wantLo)
        *reinterpret_cast<uint4*>(lo + off) = make_uint4(l[0], l[1], l[2], l[3]);
}

// ---------------------------------------------------------------------------
// cp.async.bulk 4-stage, fp16 2-pass GEMM. K/V epilogue writes rows in
// COMPACTED order via g_cpos (masked rows skipped).
// ---------------------------------------------------------------------------
constexpr int AT_B = 128 * 64;
constexpr int STG  = 3 * AT_B;
constexpr int NST  = 4;
constexpr int GEMM_SMEM = NST * STG + 64;

template <int MODE>
__global__ __launch_bounds__(256, 2) void tc_gemm(
    const float* __restrict__ b0_, const float* __restrict__ b1_,
    const float* __restrict__ b2_, const float* __restrict__ rope,
    float* __restrict__ out_ptr)
{
    extern __shared__ __align__(16) char dynsmem[];

    const int tid  = threadIdx.x;
    const int lane = tid & 31;
    const int wid  = tid >> 5;
    const int wm   = wid & 1;
    const int wn   = wid >> 1;
    const int m0   = blockIdx.y * 128;
    const int n0   = blockIdx.x * 128;

    const __half *Ahi, *Alo, *Bh;
    const float* bias;
    if (MODE == 0) {
        const int z = blockIdx.z;
        Ahi = g_xhi; Alo = g_xlo;
        Bh = g_whi + (size_t)z * C * C;
        bias = (z == 0) ? b0_ : (z == 1) ? b1_ : b2_;
    } else {
        Ahi = g_ohi; Alo = g_olo;
        Bh = g_whi + (size_t)3 * C * C;
        bias = b0_;
    }

    const uint32_t sbase = smem_u32(dynsmem);
    const uint32_t fullb = sbase + NST * STG;
    const uint32_t emptb = fullb + NST * 8;

    if (tid == 0) {
        #pragma unroll
        for (int s = 0; s < NST; s++) {
            mbar_init(fullb + s * 8, 1);
            mbar_init(emptb + s * 8, 8);
        }
    }
    __syncthreads();

    auto issue = [&](int kt) {
        const int s = kt & 3;
        const uint32_t sb = sbase + s * STG;
        const uint32_t mb = fullb + s * 8;
        mbar_expect(mb, STG);
        cp_bulk(sb,             Ahi + ((size_t)kt * M + m0) * 32, AT_B, mb);
        cp_bulk(sb + AT_B,      Alo + ((size_t)kt * M + m0) * 32, AT_B, mb);
        cp_bulk(sb + 2 * AT_B,  Bh  + ((size_t)kt * C + n0) * 32, AT_B, mb);
    };

    if (tid == 0) { issue(0); issue(1); issue(2); issue(3); }

    float acc[4][4][4];
    #pragma unroll
    for (int i = 0; i < 4; i++)
        #pragma unroll
        for (int j = 0; j < 4; j++)
            #pragma unroll
            for (int e = 0; e < 4; e++) acc[i][j][e] = 0.f;

    const int fr = (lane & 7) + ((lane >> 3) & 1) * 8;
    const int ch = (lane >> 4) & 1;
    const int raB = wm * 64 + fr;
    const int rbB = wn * 32 + fr;

    auto compute_ktile = [&](uint32_t st) {
        #pragma unroll
        for (int kf = 0; kf < 2; kf++) {
            const int c0 = kf * 2 + ch;
            uint32_t ah[4][4], bh[2][4];
            #pragma unroll
            for (int fm = 0; fm < 4; fm++) {
                const int ra = raB + fm * 16;
                ldsm_x4(ah[fm], st + ra * 64 + ((c0 ^ ((ra >> 1) & 3)) << 4));
            }
            #pragma unroll
            for (int f2 = 0; f2 < 2; f2++) {
                const int rb = rbB + f2 * 16;
                ldsm_x4(bh[f2], st + 2 * AT_B + rb * 64 + ((c0 ^ ((rb >> 1) & 3)) << 4));
            }
            #pragma unroll
            for (int fm = 0; fm < 4; fm++)
                #pragma unroll
                for (int fn = 0; fn < 4; fn++)
                    mma_f16(acc[fm][fn], ah[fm],
                            bh[fn >> 1][fn & 1], bh[fn >> 1][2 + (fn & 1)]);
            {
                uint32_t al[4][4];
                #pragma unroll
                for (int fm = 0; fm < 4; fm++) {
                    const int ra = raB + fm * 16;
                    ldsm_x4(al[fm], st + AT_B + ra * 64 + ((c0 ^ ((ra >> 1) & 3)) << 4));
                }
                #pragma unroll
                for (int fm = 0; fm < 4; fm++)
                    #pragma unroll
                    for (int fn = 0; fn < 4; fn++)
                        mma_f16(acc[fm][fn], al[fm],
                                bh[fn >> 1][fn & 1], bh[fn >> 1][2 + (fn & 1)]);
            }
        }
    };

    constexpr int NKT = K / 32;
    for (int kt = 0; kt < NKT; kt++) {
        const int s = kt & 3;
        const int p = (kt >> 2) & 1;
        mbar_wait(fullb + s * 8, p);
        compute_ktile(sbase + s * STG);
        __syncwarp();
        if (lane == 0) mbar_arrive(emptb + s * 8);
        if (wid == 0 && kt + NST < NKT) {
            mbar_wait(emptb + s * 8, p);
            if (lane == 0) issue(kt + NST);
        }
    }

    // ------------------- Epilogue -------------------
    const int gid = lane >> 2, tig = lane & 3;

    if (MODE == 0) {
        const int z = blockIdx.z;
        __half* dhi = (z == 0) ? g_qhi : (z == 1) ? g_khi : g_vhi;
        const float scale = (z == 0) ? 0.125f : 1.f;
        const bool doRope = (z < 2) && ((wn & 1) == 0);
        const int hh = (n0 >> 6) + (wn >> 1);

        #pragma unroll
        for (int fm = 0; fm < 4; fm++) {
            #pragma unroll
            for (int hf = 0; hf < 2; hf++) {
                const int m  = m0 + wm * 64 + fm * 16 + gid + hf * 8;
                const int bb = m >> 11, tt = m & (T - 1);
                // K/V: write into compacted row position (skip masked rows)
                int ttw = tt;
                if (z >= 1) ttw = g_cpos[bb * T + tt];
                float2 val[4];
                #pragma unroll
                for (int fn = 0; fn < 4; fn++) {
                    const int n = n0 + wn * 32 + fn * 8 + tig * 2;
                    val[fn].x = acc[fm][fn][hf * 2 + 0] + bias[n];
                    val[fn].y = acc[fm][fn][hf * 2 + 1] + bias[n + 1];
                }
                if (doRope) {
                    #pragma unroll
                    for (int fn = 0; fn < 2; fn++) {
                        const int i = fn * 8 + tig * 2;
                        const float2 c = *reinterpret_cast<const float2*>(rope + tt * R + i);
                        const float2 s = *reinterpret_cast<const float2*>(rope + T * R + tt * R + i);
                        const float2 x1 = val[fn], x2 = val[fn + 2];
                        val[fn].x     = x1.x * c.x - x2.x * s.x;
                        val[fn].y     = x1.y * c.y - x2.y * s.y;
                        val[fn + 2].x = x2.x * c.x + x1.x * s.x;
                        val[fn + 2].y = x2.y * c.y + x1.y * s.y;
                    }
                }
                if (ttw >= 0) {
                    #pragma unroll
                    for (int fn = 0; fn < 4; fn++) {
                        const int d = (wn & 1) * 32 + fn * 8 + tig * 2;
                        const float v0 = val[fn].x * scale, v1 = val[fn].y * scale;
                        uint32_t hv = packh(v0, v1);
                        const size_t off = (((size_t)bb * H + hh) * T + ttw) * D + d;
                        *reinterpret_cast<uint32_t*>(dhi + off) = hv;
                        if (z == 0) {
                            uint32_t lv = pack_resh(v0, v1, hv);
                            *reinterpret_cast<uint32_t*>(g_qlo + off) = lv;
                        }
                    }
                }
            }
        }
    } else {
        #pragma unroll
        for (int fm = 0; fm < 4; fm++) {
            const int mlo = m0 + wm * 64 + fm * 16 + gid;
            #pragma unroll
            for (int fn = 0; fn < 4; fn++) {
                const int n = n0 + wn * 32 + fn * 8 + tig * 2;
                const float bv0 = bias[n], bv1 = bias[n + 1];
                #pragma unroll
                for (int hf = 0; hf < 2; hf++) {
                    const int m = mlo + hf * 8;
                    float* p = out_ptr + (size_t)m * C + n;
                    p[0] = acc[fm][fn][hf * 2 + 0] + bv0;
                    p[1] = acc[fm][fn][hf * 2 + 1] + bv1;
                }
            }
        }
    }
}

// ---------------------------------------------------------------------------
// Tensor-core flash attention, fp16 2-pass, chunked. K/V already compacted:
// sequential row reads, loop bound = cnt (exact transform, ~half the steps).
// ---------------------------------------------------------------------------
constexpr int AST    = 72;
constexpr int KVTILE = 64 * AST * 2;
constexpr int KVST   = 2 * KVTILE;
constexpr int ATT_SMEM = 2 * 128 * AST * 2 + 2 * KVST + 2 * 64 * 4;

__global__ __launch_bounds__(256, 2) void attn_tc(const int* __restrict__ mask)
{
    extern __shared__ __align__(16) char asmem[];
    __half* Qh = reinterpret_cast<__half*>(asmem);
    __half* Ql = Qh + 128 * AST;
    char* KVbase = asmem + 2 * 128 * AST * 2;
    float* msks = reinterpret_cast<float*>(KVbase + 2 * KVST);

    const int tid  = threadIdx.x;
    const int lane = tid & 31, wid = tid >> 5;
    const int gid  = lane >> 2, tig = lane & 3;
    const int bh = blockIdx.y, b = bh >> 4, h = bh & 15;
    const int q0 = blockIdx.x * 128;

    const int cnt = g_cnt[b];
    const int nsteps = (cnt + 63) >> 6;

    const size_t qgbase = ((size_t)bh * T + q0) * 64;
    #pragma unroll
    for (int i = 0; i < 4; i++) {
        const int idx = tid + i * 256;
        const int row = idx >> 3, c8 = (idx & 7) * 8;
        *reinterpret_cast<float4*>(reinterpret_cast<char*>(Qh) + row * 144 + c8 * 2) =
            *reinterpret_cast<const float4*>(g_qhi + qgbase + row * 64 + c8);
        *reinterpret_cast<float4*>(reinterpret_cast<char*>(Ql) + row * 144 + c8 * 2) =
            *reinterpret_cast<const float4*>(g_qlo + qgbase + row * 64 + c8);
    }

    float4 st[4];
    const size_t kvgrow = (size_t)bh * T;
    auto ldkv = [&](int kv0) {
        #pragma unroll
        for (int i = 0; i < 4; i++) {
            const int t_ = i >> 1;
            const int idx = tid + (i & 1) * 256;
            const int row = idx >> 3, c8 = (idx & 7) * 8;
            const __half* src = (t_ == 0) ? g_khi : g_vhi;
            st[i] = *reinterpret_cast<const float4*>(src + (kvgrow + kv0 + row) * 64 + c8);
        }
    };
    auto stkv = [&](int stage, int kv0) {
        char* sb = KVbase + stage * KVST;
        #pragma unroll
        for (int i = 0; i < 4; i++) {
            const int t_ = i >> 1;
            const int idx = tid + (i & 1) * 256;
            const int row = idx >> 3, c8 = (idx & 7) * 8;
            *reinterpret_cast<float4*>(sb + t_ * KVTILE + row * 144 + c8 * 2) = st[i];
        }
        if (tid < 64) msks[stage * 64 + tid] = (kv0 + tid < cnt) ? 0.f : -1e30f;
    };

    ldkv(0);
    __syncthreads();
    stkv(0, 0);
    __syncthreads();

    uint32_t qh[4][4], ql[4][4];
    {
        const uint32_t qhb = smem_u32(Qh), qlb = smem_u32(Ql);
        const int qr = wid * 16 + (lane & 15);
        const int qc = (lane >> 4) * 16;
        #pragma unroll
        for (int kc = 0; kc < 4; kc++) {
            ldsm_x4(qh[kc], qhb + qr * 144 + kc * 32 + qc);
            ldsm_x4(ql[kc], qlb + qr * 144 + kc * 32 + qc);
        }
    }

    float of[8][4];
    #pragma unroll
    for (int i = 0; i < 8; i++)
        #pragma unroll
        for (int e = 0; e < 4; e++) of[i][e] = 0.f;
    float li0 = 0.f, li1 = 0.f;

    const uint32_t kvb0 = smem_u32(KVbase);
    const int lr = lane & 15;
    const int lc = (lane >> 4) * 16;

    for (int kt = 0; kt < nsteps; kt++) {
        if (kt + 1 < nsteps) ldkv((kt + 1) * 64);

        const int s = kt & 1;
        const uint32_t khb = kvb0 + s * KVST;
        const uint32_t vhb = khb + KVTILE;

        #pragma unroll
        for (int chunk = 0; chunk < 2; chunk++) {
            float sf[4][4];
            #pragma unroll
            for (int i = 0; i < 4; i++)
                #pragma unroll
                for (int e = 0; e < 4; e++) sf[i][e] = 0.f;

            #pragma unroll
            for (int kc = 0; kc < 4; kc++) {
                #pragma unroll
                for (int ng = 0; ng < 2; ng++) {
                    uint32_t kb[4];
                    const uint32_t a = (chunk * 32 + ng * 16 + lr) * 144 + kc * 32 + lc;
                    ldsm_x4(kb, khb + a);
                    mma_f16(sf[2 * ng],     qh[kc], kb[0], kb[2]);
                    mma_f16(sf[2 * ng],     ql[kc], kb[0], kb[2]);
                    mma_f16(sf[2 * ng + 1], qh[kc], kb[1], kb[3]);
                    mma_f16(sf[2 * ng + 1], ql[kc], kb[1], kb[3]);
                }
            }

            float r0 = 0.f, r1 = 0.f;
            #pragma unroll
            for (int nf = 0; nf < 4; nf++) {
                const float m0 = msks[s * 64 + chunk * 32 + nf * 8 + tig * 2];
                const float m1 = msks[s * 64 + chunk * 32 + nf * 8 + tig * 2 + 1];
                const float e0 = __expf(sf[nf][0] + m0);
                const float e1 = __expf(sf[nf][1] + m1);
                const float e2 = __expf(sf[nf][2] + m0);
                const float e3 = __expf(sf[nf][3] + m1);
                sf[nf][0] = e0; sf[nf][1] = e1; sf[nf][2] = e2; sf[nf][3] = e3;
                r0 += e0 + e1; r1 += e2 + e3;
            }
            r0 += __shfl_xor_sync(0xffffffffu, r0, 1);
            r0 += __shfl_xor_sync(0xffffffffu, r0, 2);
            r1 += __shfl_xor_sync(0xffffffffu, r1, 1);
            r1 += __shfl_xor_sync(0xffffffffu, r1, 2);
            li0 += r0; li1 += r1;

            uint32_t ah[2][4], al[2][4];
            #pragma unroll
            for (int kc2 = 0; kc2 < 2; kc2++) {
                const float* eA = sf[2 * kc2];
                const float* eB = sf[2 * kc2 + 1];
                ah[kc2][0] = packh(eA[0], eA[1]);
                ah[kc2][1] = packh(eA[2], eA[3]);
                ah[kc2][2] = packh(eB[0], eB[1]);
                ah[kc2][3] = packh(eB[2], eB[3]);
                al[kc2][0] = pack_resh(eA[0], eA[1], ah[kc2][0]);
                al[kc2][1] = pack_resh(eA[2], eA[3], ah[kc2][1]);
                al[kc2][2] = pack_resh(eB[0], eB[1], ah[kc2][2]);
                al[kc2][3] = pack_resh(eB[2], eB[3], ah[kc2][3]);
            }

            #pragma unroll
            for (int kc2 = 0; kc2 < 2; kc2++) {
                #pragma unroll
                for (int dg = 0; dg < 4; dg++) {
                    uint32_t vb[4];
                    const uint32_t a = (chunk * 32 + kc2 * 16 + lr) * 144 + dg * 32 + lc;
                    ldsm_x4_t(vb, vhb + a);
                    mma_f16(of[2 * dg],     ah[kc2], vb[0], vb[1]);
                    mma_f16(of[2 * dg],     al[kc2], vb[0], vb[1]);
                    mma_f16(of[2 * dg + 1], ah[kc2], vb[2], vb[3]);
                    mma_f16(of[2 * dg + 1], al[kc2], vb[2], vb[3]);
                }
            }
        }

        if (kt + 1 < nsteps) stkv((kt + 1) & 1, (kt + 1) * 64);
        __syncthreads();
    }

    // normalize + split to fp16 hi/lo, write blocked-swizzled [ktile][m][32]
    const float i0 = 1.f / li0, i1 = 1.f / li1;
    const int r0w = q0 + wid * 16 + gid;
    const int r1w = r0w + 8;
    const int ma = b * T + r0w, mb = b * T + r1w;
    #pragma unroll
    for (int df = 0; df < 8; df++) {
        const int c   = h * 64 + df * 8 + tig * 2;
        const int ktc = c >> 5, cin = (c >> 3) & 3, el = c & 7;
        const size_t oa = ((size_t)ktc * M + ma) * 32 + ((cin ^ ((ma >> 1) & 3)) << 3) + el;
        const size_t ob = ((size_t)ktc * M + mb) * 32 + ((cin ^ ((mb >> 1) & 3)) << 3) + el;
        const float v0 = of[df][0] * i0, v1 = of[df][1] * i0;
        const float v2 = of[df][2] * i1, v3 = of[df][3] * i1;
        uint32_t h0 = packh(v0, v1);
        uint32_t l0 = pack_resh(v0, v1, h0);
        uint32_t h1 = packh(v2, v3);
        uint32_t l1 = pack_resh(v2, v3, h1);
        *reinterpret_cast<uint32_t*>(g_ohi + oa) = h0;
        *reinterpret_cast<uint32_t*>(g_olo + oa) = l0;
        *reinterpret_cast<uint32_t*>(g_ohi + ob) = h1;
        *reinterpret_cast<uint32_t*>(g_olo + ob) = l1;
    }
}

// ---------------------------------------------------------------------------
extern "C" void kernel_launch(void* const* d_in, const int* in_sizes, int n_in,
                              void* d_out, int out_size)
{
    const float* x    = (const float*)d_in[0];
    const float* rope = (const float*)d_in[1];
    const int*   mask = (const int*)  d_in[2];
    const float* Wq = (const float*)d_in[3];
    const float* bq = (const float*)d_in[4];
    const float* Wk = (const float*)d_in[5];
    const float* bk = (const float*)d_in[6];
    const float* Wv = (const float*)d_in[7];
    const float* bv = (const float*)d_in[8];
    const float* Wo = (const float*)d_in[9];
    const float* bo = (const float*)d_in[10];
    float* out = (float*)d_out;

    // Mask compaction (tiny) + merged split
    compact_mask<<<B, 256>>>(mask);
    split_all<<<4096 + 4 * 512, 256>>>(x, Wq, Wk, Wv, Wo);

    // QKV projections (K/V written compacted)
    cudaFuncSetAttribute(tc_gemm<0>, cudaFuncAttributeMaxDynamicSharedMemorySize, GEMM_SMEM);
    cudaFuncSetAttribute(tc_gemm<1>, cudaFuncAttributeMaxDynamicSharedMemorySize, GEMM_SMEM);
    tc_gemm<0><<<dim3(C / 128, M / 128, 3), 256, GEMM_SMEM>>>(bq, bk, bv, rope, nullptr);

    // Tensor-core attention over compacted keys (sequential reads)
    cudaFuncSetAttribute(attn_tc, cudaFuncAttributeMaxDynamicSharedMemorySize, ATT_SMEM);
    attn_tc<<<dim3(T / 128, B * H), 256, ATT_SMEM>>>(mask);

    // Output projection
    tc_gemm<1><<<dim3(C / 128, M / 128, 1), 256, GEMM_SMEM>>>(bo, nullptr, nullptr, nullptr, out);
}

// round 17
// speedup vs baseline: 1.7451x; 1.1239x over previous
#include <cuda_runtime.h>
#include <cuda_fp16.h>
#include <math.h>
#include <cstdint>

// Problem constants
namespace {
constexpr int B = 4, T = 2048, C = 1024, H = 16, D = 64, R = 32;
constexpr int M = B * T;   // 8192
constexpr int K = C;       // 1024
}

// Scratch (device globals — no allocation allowed)
__device__ __half g_xhi[M * C], g_xlo[M * C];
__device__ __half g_xchi[M * C], g_xclo[M * C];      // x rows compacted per batch
__device__ __half g_whi[4 * C * C];                  // Wq,Wk,Wv,Wo (hi only)
__device__ __half g_ohi[M * C], g_olo[M * C];
__device__ __half g_qhi[B * H * T * D], g_qlo[B * H * T * D];
__device__ __half g_khi[B * H * T * D];              // hi only, COMPACTED rows
__device__ __half g_vhi[B * H * T * D];              // hi only, COMPACTED rows
// Mask compaction maps
__device__ int g_cpos[B * T];    // orig row -> compact pos (-1 if masked)
__device__ int g_cidx[B * T];    // compact pos -> orig row
__device__ int g_cnt[B];

// ---------------------------------------------------------------------------
// Helpers
// ---------------------------------------------------------------------------
__device__ __forceinline__ uint32_t smem_u32(const void* p) {
    uint32_t a;
    asm("{ .reg .u64 t; cvta.to.shared.u64 t, %1; cvt.u32.u64 %0, t; }"
        : "=r"(a) : "l"(p));
    return a;
}

__device__ __forceinline__ void ldsm_x4(uint32_t* r, uint32_t addr) {
    asm volatile("ldmatrix.sync.aligned.m8n8.x4.shared.b16 {%0,%1,%2,%3}, [%4];"
                 : "=r"(r[0]), "=r"(r[1]), "=r"(r[2]), "=r"(r[3]) : "r"(addr));
}
__device__ __forceinline__ void ldsm_x4_t(uint32_t* r, uint32_t addr) {
    asm volatile("ldmatrix.sync.aligned.m8n8.x4.trans.shared.b16 {%0,%1,%2,%3}, [%4];"
                 : "=r"(r[0]), "=r"(r[1]), "=r"(r[2]), "=r"(r[3]) : "r"(addr));
}

__device__ __forceinline__ void mma_f16(float* c, const uint32_t* a,
                                        uint32_t b0, uint32_t b1) {
    asm volatile(
        "mma.sync.aligned.m16n8k16.row.col.f32.f16.f16.f32 "
        "{%0,%1,%2,%3}, {%4,%5,%6,%7}, {%8,%9}, {%0,%1,%2,%3};"
        : "+f"(c[0]), "+f"(c[1]), "+f"(c[2]), "+f"(c[3])
        : "r"(a[0]), "r"(a[1]), "r"(a[2]), "r"(a[3]), "r"(b0), "r"(b1));
}

__device__ __forceinline__ uint32_t packh(float a, float b) {
    __half2 t = __floats2half2_rn(a, b);
    return *reinterpret_cast<uint32_t*>(&t);
}
__device__ __forceinline__ uint32_t pack_resh(float a, float b, uint32_t hp) {
    __half2 hv = *reinterpret_cast<__half2*>(&hp);
    return packh(a - __half2float(hv.x), b - __half2float(hv.y));
}

// --- bulk copy + mbarrier (sm_90 base features) ---
__device__ __forceinline__ void cp_bulk(uint32_t dst, const void* src,
                                        uint32_t bytes, uint32_t mbar) {
    asm volatile(
        "cp.async.bulk.shared::cluster.global.mbarrier::complete_tx::bytes "
        "[%0], [%1], %2, [%3];"
        :: "r"(dst), "l"(src), "r"(bytes), "r"(mbar) : "memory");
}
__device__ __forceinline__ void mbar_init(uint32_t addr, uint32_t cnt) {
    asm volatile("mbarrier.init.shared.b64 [%0], %1;" :: "r"(addr), "r"(cnt) : "memory");
}
__device__ __forceinline__ void mbar_expect(uint32_t addr, uint32_t bytes) {
    asm volatile("mbarrier.arrive.expect_tx.shared.b64 _, [%0], %1;"
                 :: "r"(addr), "r"(bytes) : "memory");
}
__device__ __forceinline__ void mbar_arrive(uint32_t addr) {
    asm volatile("mbarrier.arrive.shared.b64 _, [%0];" :: "r"(addr) : "memory");
}
__device__ __forceinline__ void mbar_wait(uint32_t addr, uint32_t parity) {
    asm volatile(
        "{\n\t.reg .pred P;\n\t"
        "WL_%=:\n\t"
        "mbarrier.try_wait.parity.acquire.cta.shared::cta.b64 P, [%0], %1, 0x989680;\n\t"
        "@P bra.uni WD_%=;\n\t"
        "bra.uni WL_%=;\n\t"
        "WD_%=:\n\t}"
        :: "r"(addr), "r"(parity) : "memory");
}

// ---------------------------------------------------------------------------
// Mask compaction: per batch, forward + inverse maps and count.
// ---------------------------------------------------------------------------
__global__ void compact_mask(const int* __restrict__ mask) {
    const int b = blockIdx.x;
    const int tid = threadIdx.x;
    __shared__ int ssum[256];
    int loc[8];
    int cnt = 0;
    const int base = b * T + tid * 8;
    int mv[8];
    #pragma unroll
    for (int i = 0; i < 8; i++) {
        mv[i] = mask[base + i];
        loc[i] = cnt;
        cnt += (mv[i] != 0);
    }
    ssum[tid] = cnt;
    __syncthreads();
    for (int off = 1; off < 256; off <<= 1) {
        int v = (tid >= off) ? ssum[tid - off] : 0;
        __syncthreads();
        ssum[tid] += v;
        __syncthreads();
    }
    const int pre = (tid == 0) ? 0 : ssum[tid - 1];
    #pragma unroll
    for (int i = 0; i < 8; i++) {
        const int cp = mv[i] ? (pre + loc[i]) : -1;
        g_cpos[base + i] = cp;
        if (cp >= 0) g_cidx[b * T + cp] = tid * 8 + i;
    }
    if (tid == 255) g_cnt[b] = ssum[255];
}

// ---------------------------------------------------------------------------
// Merged split: fp32 -> fp16 hi(/lo) into blocked-swizzled layout.
// x additionally written to COMPACTED row order (g_xchi/g_xclo) for K/V GEMMs.
// ---------------------------------------------------------------------------
__global__ void split_all(const float* __restrict__ x,
                          const float* __restrict__ Wq,
                          const float* __restrict__ Wk,
                          const float* __restrict__ Wv,
                          const float* __restrict__ Wo) {
    const int bx = blockIdx.x;
    const float* src;
    __half *hi, *lo = nullptr;
    int rows, base;
    bool isX;
    if (bx < 4096) {
        src = x; hi = g_xhi; lo = g_xlo; rows = M; base = 0; isX = true;
    } else {
        const int j = (bx - 4096) >> 9;
        base = 4096 + (j << 9);
        src = (j == 0) ? Wq : (j == 1) ? Wk : (j == 2) ? Wv : Wo;
        hi = g_whi + (size_t)j * C * C;
        rows = C; isX = false;
    }
    const int idx = (bx - base) * 256 + threadIdx.x;
    const int m  = idx >> 7;
    const int kc = idx & 127;
    const float4* p = reinterpret_cast<const float4*>(src + (size_t)m * 1024 + kc * 8);
    float4 a = p[0], b = p[1];
    uint32_t h[4], l[4];
    h[0] = packh(a.x, a.y); l[0] = pack_resh(a.x, a.y, h[0]);
    h[1] = packh(a.z, a.w); l[1] = pack_resh(a.z, a.w, h[1]);
    h[2] = packh(b.x, b.y); l[2] = pack_resh(b.x, b.y, h[2]);
    h[3] = packh(b.z, b.w); l[3] = pack_resh(b.z, b.w, h[3]);
    const int kt = kc >> 2, cin = kc & 3;
    const int swz = cin ^ ((m >> 1) & 3);
    const size_t off = ((size_t)kt * rows + m) * 32 + swz * 8;
    *reinterpret_cast<uint4*>(hi + off) = make_uint4(h[0], h[1], h[2], h[3]);
    if (isX) {
        *reinterpret_cast<uint4*>(lo + off) = make_uint4(l[0], l[1], l[2], l[3]);
        const int cp = g_cpos[m];
        if (cp >= 0) {
            const int bb = m >> 11;
            const int mc = bb * T + cp;
            const int swzc = cin ^ ((mc >> 1) & 3);
            const size_t offc = ((size_t)kt * M + mc) * 32 + swzc * 8;
            *reinterpret_cast<uint4*>(g_xchi + offc) = make_uint4(h[0], h[1], h[2], h[3]);
            *reinterpret_cast<uint4*>(g_xclo + offc) = make_uint4(l[0], l[1], l[2], l[3]);
        }
    }
}

// ---------------------------------------------------------------------------
// cp.async.bulk 4-stage, fp16 2-pass GEMM.
// MODE 0, z=0: Q projection over all rows (RoPE + hi/lo epilogue).
// MODE 0, z>=1: K/V projection over COMPACTED x rows; blocks fully beyond
//               cnt[b] exit immediately. Epilogue writes K/V sequentially at
//               compacted positions; K's RoPE uses orig t via g_cidx.
// MODE 1: out-projection, fp32 + bias into d_out.
// ---------------------------------------------------------------------------
constexpr int AT_B = 128 * 64;
constexpr int STG  = 3 * AT_B;
constexpr int NST  = 4;
constexpr int GEMM_SMEM = NST * STG + 64;

template <int MODE>
__global__ __launch_bounds__(256, 2) void tc_gemm(
    const float* __restrict__ b0_, const float* __restrict__ b1_,
    const float* __restrict__ b2_, const float* __restrict__ rope,
    float* __restrict__ out_ptr)
{
    extern __shared__ __align__(16) char dynsmem[];

    const int tid  = threadIdx.x;
    const int lane = tid & 31;
    const int wid  = tid >> 5;
    const int wm   = wid & 1;
    const int wn   = wid >> 1;
    const int m0   = blockIdx.y * 128;
    const int n0   = blockIdx.x * 128;

    const __half *Ahi, *Alo, *Bh;
    const float* bias;
    bool compacted = false;
    int cntb = 0;
    if (MODE == 0) {
        const int z = blockIdx.z;
        if (z == 0) {
            Ahi = g_xhi; Alo = g_xlo;
        } else {
            compacted = true;
            cntb = g_cnt[m0 >> 11];
            if ((m0 & (T - 1)) >= cntb) return;   // whole block masked away
            Ahi = g_xchi; Alo = g_xclo;
        }
        Bh = g_whi + (size_t)z * C * C;
        bias = (z == 0) ? b0_ : (z == 1) ? b1_ : b2_;
    } else {
        Ahi = g_ohi; Alo = g_olo;
        Bh = g_whi + (size_t)3 * C * C;
        bias = b0_;
    }

    const uint32_t sbase = smem_u32(dynsmem);
    const uint32_t fullb = sbase + NST * STG;
    const uint32_t emptb = fullb + NST * 8;

    if (tid == 0) {
        #pragma unroll
        for (int s = 0; s < NST; s++) {
            mbar_init(fullb + s * 8, 1);
            mbar_init(emptb + s * 8, 8);
        }
    }
    __syncthreads();

    auto issue = [&](int kt) {
        const int s = kt & 3;
        const uint32_t sb = sbase + s * STG;
        const uint32_t mb = fullb + s * 8;
        mbar_expect(mb, STG);
        cp_bulk(sb,             Ahi + ((size_t)kt * M + m0) * 32, AT_B, mb);
        cp_bulk(sb + AT_B,      Alo + ((size_t)kt * M + m0) * 32, AT_B, mb);
        cp_bulk(sb + 2 * AT_B,  Bh  + ((size_t)kt * C + n0) * 32, AT_B, mb);
    };

    if (tid == 0) { issue(0); issue(1); issue(2); issue(3); }

    float acc[4][4][4];
    #pragma unroll
    for (int i = 0; i < 4; i++)
        #pragma unroll
        for (int j = 0; j < 4; j++)
            #pragma unroll
            for (int e = 0; e < 4; e++) acc[i][j][e] = 0.f;

    const int fr = (lane & 7) + ((lane >> 3) & 1) * 8;
    const int ch = (lane >> 4) & 1;
    const int raB = wm * 64 + fr;
    const int rbB = wn * 32 + fr;

    auto compute_ktile = [&](uint32_t st) {
        #pragma unroll
        for (int kf = 0; kf < 2; kf++) {
            const int c0 = kf * 2 + ch;
            uint32_t ah[4][4], bh[2][4];
            #pragma unroll
            for (int fm = 0; fm < 4; fm++) {
                const int ra = raB + fm * 16;
                ldsm_x4(ah[fm], st + ra * 64 + ((c0 ^ ((ra >> 1) & 3)) << 4));
            }
            #pragma unroll
            for (int f2 = 0; f2 < 2; f2++) {
                const int rb = rbB + f2 * 16;
                ldsm_x4(bh[f2], st + 2 * AT_B + rb * 64 + ((c0 ^ ((rb >> 1) & 3)) << 4));
            }
            #pragma unroll
            for (int fm = 0; fm < 4; fm++)
                #pragma unroll
                for (int fn = 0; fn < 4; fn++)
                    mma_f16(acc[fm][fn], ah[fm],
                            bh[fn >> 1][fn & 1], bh[fn >> 1][2 + (fn & 1)]);
            {
                uint32_t al[4][4];
                #pragma unroll
                for (int fm = 0; fm < 4; fm++) {
                    const int ra = raB + fm * 16;
                    ldsm_x4(al[fm], st + AT_B + ra * 64 + ((c0 ^ ((ra >> 1) & 3)) << 4));
                }
                #pragma unroll
                for (int fm = 0; fm < 4; fm++)
                    #pragma unroll
                    for (int fn = 0; fn < 4; fn++)
                        mma_f16(acc[fm][fn], al[fm],
                                bh[fn >> 1][fn & 1], bh[fn >> 1][2 + (fn & 1)]);
            }
        }
    };

    constexpr int NKT = K / 32;
    for (int kt = 0; kt < NKT; kt++) {
        const int s = kt & 3;
        const int p = (kt >> 2) & 1;
        mbar_wait(fullb + s * 8, p);
        compute_ktile(sbase + s * STG);
        __syncwarp();
        if (lane == 0) mbar_arrive(emptb + s * 8);
        if (wid == 0 && kt + NST < NKT) {
            mbar_wait(emptb + s * 8, p);
            if (lane == 0) issue(kt + NST);
        }
    }

    // ------------------- Epilogue -------------------
    const int gid = lane >> 2, tig = lane & 3;

    if (MODE == 0) {
        const int z = blockIdx.z;
        __half* dhi = (z == 0) ? g_qhi : (z == 1) ? g_khi : g_vhi;
        const float scale = (z == 0) ? 0.125f : 1.f;
        const bool doRope = (z < 2) && ((wn & 1) == 0);
        const int hh = (n0 >> 6) + (wn >> 1);

        #pragma unroll
        for (int fm = 0; fm < 4; fm++) {
            #pragma unroll
            for (int hf = 0; hf < 2; hf++) {
                const int m  = m0 + wm * 64 + fm * 16 + gid + hf * 8;
                const int bb = m >> 11, tt = m & (T - 1);
                // RoPE time index: orig row for compacted K rows
                int trope = tt;
                if (compacted) trope = (tt < cntb) ? g_cidx[bb * T + tt] : 0;
                float2 val[4];
                #pragma unroll
                for (int fn = 0; fn < 4; fn++) {
                    const int n = n0 + wn * 32 + fn * 8 + tig * 2;
                    val[fn].x = acc[fm][fn][hf * 2 + 0] + bias[n];
                    val[fn].y = acc[fm][fn][hf * 2 + 1] + bias[n + 1];
                }
                if (doRope) {
                    #pragma unroll
                    for (int fn = 0; fn < 2; fn++) {
                        const int i = fn * 8 + tig * 2;
                        const float2 c = *reinterpret_cast<const float2*>(rope + trope * R + i);
                        const float2 s = *reinterpret_cast<const float2*>(rope + T * R + trope * R + i);
                        const float2 x1 = val[fn], x2 = val[fn + 2];
                        val[fn].x     = x1.x * c.x - x2.x * s.x;
                        val[fn].y     = x1.y * c.y - x2.y * s.y;
                        val[fn + 2].x = x2.x * c.x + x1.x * s.x;
                        val[fn + 2].y = x2.y * c.y + x1.y * s.y;
                    }
                }
                #pragma unroll
                for (int fn = 0; fn < 4; fn++) {
                    const int d = (wn & 1) * 32 + fn * 8 + tig * 2;
                    const float v0 = val[fn].x * scale, v1 = val[fn].y * scale;
                    uint32_t hv = packh(v0, v1);
                    const size_t off = (((size_t)bb * H + hh) * T + tt) * D + d;
                    *reinterpret_cast<uint32_t*>(dhi + off) = hv;
                    if (z == 0) {
                        uint32_t lv = pack_resh(v0, v1, hv);
                        *reinterpret_cast<uint32_t*>(g_qlo + off) = lv;
                    }
                }
            }
        }
    } else {
        #pragma unroll
        for (int fm = 0; fm < 4; fm++) {
            const int mlo = m0 + wm * 64 + fm * 16 + gid;
            #pragma unroll
            for (int fn = 0; fn < 4; fn++) {
                const int n = n0 + wn * 32 + fn * 8 + tig * 2;
                const float bv0 = bias[n], bv1 = bias[n + 1];
                #pragma unroll
                for (int hf = 0; hf < 2; hf++) {
                    const int m = mlo + hf * 8;
                    float* p = out_ptr + (size_t)m * C + n;
                    p[0] = acc[fm][fn][hf * 2 + 0] + bv0;
                    p[1] = acc[fm][fn][hf * 2 + 1] + bv1;
                }
            }
        }
    }
}

// ---------------------------------------------------------------------------
// Tensor-core flash attention, fp16 2-pass, chunked, compacted K/V
// (round-16 proven, unchanged).
// ---------------------------------------------------------------------------
constexpr int AST    = 72;
constexpr int KVTILE = 64 * AST * 2;
constexpr int KVST   = 2 * KVTILE;
constexpr int ATT_SMEM = 2 * 128 * AST * 2 + 2 * KVST + 2 * 64 * 4;

__global__ __launch_bounds__(256, 2) void attn_tc(const int* __restrict__ mask)
{
    extern __shared__ __align__(16) char asmem[];
    __half* Qh = reinterpret_cast<__half*>(asmem);
    __half* Ql = Qh + 128 * AST;
    char* KVbase = asmem + 2 * 128 * AST * 2;
    float* msks = reinterpret_cast<float*>(KVbase + 2 * KVST);

    const int tid  = threadIdx.x;
    const int lane = tid & 31, wid = tid >> 5;
    const int gid  = lane >> 2, tig = lane & 3;
    const int bh = blockIdx.y, b = bh >> 4, h = bh & 15;
    const int q0 = blockIdx.x * 128;

    const int cnt = g_cnt[b];
    const int nsteps = (cnt + 63) >> 6;

    const size_t qgbase = ((size_t)bh * T + q0) * 64;
    #pragma unroll
    for (int i = 0; i < 4; i++) {
        const int idx = tid + i * 256;
        const int row = idx >> 3, c8 = (idx & 7) * 8;
        *reinterpret_cast<float4*>(reinterpret_cast<char*>(Qh) + row * 144 + c8 * 2) =
            *reinterpret_cast<const float4*>(g_qhi + qgbase + row * 64 + c8);
        *reinterpret_cast<float4*>(reinterpret_cast<char*>(Ql) + row * 144 + c8 * 2) =
            *reinterpret_cast<const float4*>(g_qlo + qgbase + row * 64 + c8);
    }

    float4 st[4];
    const size_t kvgrow = (size_t)bh * T;
    auto ldkv = [&](int kv0) {
        #pragma unroll
        for (int i = 0; i < 4; i++) {
            const int t_ = i >> 1;
            const int idx = tid + (i & 1) * 256;
            const int row = idx >> 3, c8 = (idx & 7) * 8;
            const __half* src = (t_ == 0) ? g_khi : g_vhi;
            st[i] = *reinterpret_cast<const float4*>(src + (kvgrow + kv0 + row) * 64 + c8);
        }
    };
    auto stkv = [&](int stage, int kv0) {
        char* sb = KVbase + stage * KVST;
        #pragma unroll
        for (int i = 0; i < 4; i++) {
            const int t_ = i >> 1;
            const int idx = tid + (i & 1) * 256;
            const int row = idx >> 3, c8 = (idx & 7) * 8;
            *reinterpret_cast<float4*>(sb + t_ * KVTILE + row * 144 + c8 * 2) = st[i];
        }
        if (tid < 64) msks[stage * 64 + tid] = (kv0 + tid < cnt) ? 0.f : -1e30f;
    };

    ldkv(0);
    __syncthreads();
    stkv(0, 0);
    __syncthreads();

    uint32_t qh[4][4], ql[4][4];
    {
        const uint32_t qhb = smem_u32(Qh), qlb = smem_u32(Ql);
        const int qr = wid * 16 + (lane & 15);
        const int qc = (lane >> 4) * 16;
        #pragma unroll
        for (int kc = 0; kc < 4; kc++) {
            ldsm_x4(qh[kc], qhb + qr * 144 + kc * 32 + qc);
            ldsm_x4(ql[kc], qlb + qr * 144 + kc * 32 + qc);
        }
    }

    float of[8][4];
    #pragma unroll
    for (int i = 0; i < 8; i++)
        #pragma unroll
        for (int e = 0; e < 4; e++) of[i][e] = 0.f;
    float li0 = 0.f, li1 = 0.f;

    const uint32_t kvb0 = smem_u32(KVbase);
    const int lr = lane & 15;
    const int lc = (lane >> 4) * 16;

    for (int kt = 0; kt < nsteps; kt++) {
        if (kt + 1 < nsteps) ldkv((kt + 1) * 64);

        const int s = kt & 1;
        const uint32_t khb = kvb0 + s * KVST;
        const uint32_t vhb = khb + KVTILE;

        #pragma unroll
        for (int chunk = 0; chunk < 2; chunk++) {
            float sf[4][4];
            #pragma unroll
            for (int i = 0; i < 4; i++)
                #pragma unroll
                for (int e = 0; e < 4; e++) sf[i][e] = 0.f;

            #pragma unroll
            for (int kc = 0; kc < 4; kc++) {
                #pragma unroll
                for (int ng = 0; ng < 2; ng++) {
                    uint32_t kb[4];
                    const uint32_t a = (chunk * 32 + ng * 16 + lr) * 144 + kc * 32 + lc;
                    ldsm_x4(kb, khb + a);
                    mma_f16(sf[2 * ng],     qh[kc], kb[0], kb[2]);
                    mma_f16(sf[2 * ng],     ql[kc], kb[0], kb[2]);
                    mma_f16(sf[2 * ng + 1], qh[kc], kb[1], kb[3]);
                    mma_f16(sf[2 * ng + 1], ql[kc], kb[1], kb[3]);
                }
            }

            float r0 = 0.f, r1 = 0.f;
            #pragma unroll
            for (int nf = 0; nf < 4; nf++) {
                const float m0 = msks[s * 64 + chunk * 32 + nf * 8 + tig * 2];
                const float m1 = msks[s * 64 + chunk * 32 + nf * 8 + tig * 2 + 1];
                const float e0 = __expf(sf[nf][0] + m0);
                const float e1 = __expf(sf[nf][1] + m1);
                const float e2 = __expf(sf[nf][2] + m0);
                const float e3 = __expf(sf[nf][3] + m1);
                sf[nf][0] = e0; sf[nf][1] = e1; sf[nf][2] = e2; sf[nf][3] = e3;
                r0 += e0 + e1; r1 += e2 + e3;
            }
            r0 += __shfl_xor_sync(0xffffffffu, r0, 1);
            r0 += __shfl_xor_sync(0xffffffffu, r0, 2);
            r1 += __shfl_xor_sync(0xffffffffu, r1, 1);
            r1 += __shfl_xor_sync(0xffffffffu, r1, 2);
            li0 += r0; li1 += r1;

            uint32_t ah[2][4], al[2][4];
            #pragma unroll
            for (int kc2 = 0; kc2 < 2; kc2++) {
                const float* eA = sf[2 * kc2];
                const float* eB = sf[2 * kc2 + 1];
                ah[kc2][0] = packh(eA[0], eA[1]);
                ah[kc2][1] = packh(eA[2], eA[3]);
                ah[kc2][2] = packh(eB[0], eB[1]);
                ah[kc2][3] = packh(eB[2], eB[3]);
                al[kc2][0] = pack_resh(eA[0], eA[1], ah[kc2][0]);
                al[kc2][1] = pack_resh(eA[2], eA[3], ah[kc2][1]);
                al[kc2][2] = pack_resh(eB[0], eB[1], ah[kc2][2]);
                al[kc2][3] = pack_resh(eB[2], eB[3], ah[kc2][3]);
            }

            #pragma unroll
            for (int kc2 = 0; kc2 < 2; kc2++) {
                #pragma unroll
                for (int dg = 0; dg < 4; dg++) {
                    uint32_t vb[4];
                    const uint32_t a = (chunk * 32 + kc2 * 16 + lr) * 144 + dg * 32 + lc;
                    ldsm_x4_t(vb, vhb + a);
                    mma_f16(of[2 * dg],     ah[kc2], vb[0], vb[1]);
                    mma_f16(of[2 * dg],     al[kc2], vb[0], vb[1]);
                    mma_f16(of[2 * dg + 1], ah[kc2], vb[2], vb[3]);
                    mma_f16(of[2 * dg + 1], al[kc2], vb[2], vb[3]);
                }
            }
        }

        if (kt + 1 < nsteps) stkv((kt + 1) & 1, (kt + 1) * 64);
        __syncthreads();
    }

    // normalize + split to fp16 hi/lo, write blocked-swizzled [ktile][m][32]
    const float i0 = 1.f / li0, i1 = 1.f / li1;
    const int r0w = q0 + wid * 16 + gid;
    const int r1w = r0w + 8;
    const int ma = b * T + r0w, mb = b * T + r1w;
    #pragma unroll
    for (int df = 0; df < 8; df++) {
        const int c   = h * 64 + df * 8 + tig * 2;
        const int ktc = c >> 5, cin = (c >> 3) & 3, el = c & 7;
        const size_t oa = ((size_t)ktc * M + ma) * 32 + ((cin ^ ((ma >> 1) & 3)) << 3) + el;
        const size_t ob = ((size_t)ktc * M + mb) * 32 + ((cin ^ ((mb >> 1) & 3)) << 3) + el;
        const float v0 = of[df][0] * i0, v1 = of[df][1] * i0;
        const float v2 = of[df][2] * i1, v3 = of[df][3] * i1;
        uint32_t h0 = packh(v0, v1);
        uint32_t l0 = pack_resh(v0, v1, h0);
        uint32_t h1 = packh(v2, v3);
        uint32_t l1 = pack_resh(v2, v3, h1);
        *reinterpret_cast<uint32_t*>(g_ohi + oa) = h0;
        *reinterpret_cast<uint32_t*>(g_olo + oa) = l0;
        *reinterpret_cast<uint32_t*>(g_ohi + ob) = h1;
        *reinterpret_cast<uint32_t*>(g_olo + ob) = l1;
    }
}

// ---------------------------------------------------------------------------
extern "C" void kernel_launch(void* const* d_in, const int* in_sizes, int n_in,
                              void* d_out, int out_size)
{
    const float* x    = (const float*)d_in[0];
    const float* rope = (const float*)d_in[1];
    const int*   mask = (const int*)  d_in[2];
    const float* Wq = (const float*)d_in[3];
    const float* bq = (const float*)d_in[4];
    const float* Wk = (const float*)d_in[5];
    const float* bk = (const float*)d_in[6];
    const float* Wv = (const float*)d_in[7];
    const float* bv = (const float*)d_in[8];
    const float* Wo = (const float*)d_in[9];
    const float* bo = (const float*)d_in[10];
    float* out = (float*)d_out;

    // Mask compaction (tiny) + merged split (x also written compacted)
    compact_mask<<<B, 256>>>(mask);
    split_all<<<4096 + 4 * 512, 256>>>(x, Wq, Wk, Wv, Wo);

    // QKV projections (K/V over compacted rows; ~half their blocks exit)
    cudaFuncSetAttribute(tc_gemm<0>, cudaFuncAttributeMaxDynamicSharedMemorySize, GEMM_SMEM);
    cudaFuncSetAttribute(tc_gemm<1>, cudaFuncAttributeMaxDynamicSharedMemorySize, GEMM_SMEM);
    tc_gemm<0><<<dim3(C / 128, M / 128, 3), 256, GEMM_SMEM>>>(bq, bk, bv, rope, nullptr);

    // Tensor-core attention over compacted keys
    cudaFuncSetAttribute(attn_tc, cudaFuncAttributeMaxDynamicSharedMemorySize, ATT_SMEM);
    attn_tc<<<dim3(T / 128, B * H), 256, ATT_SMEM>>>(mask);

    // Output projection
    tc_gemm<1><<<dim3(C / 128, M / 128, 1), 256, GEMM_SMEM>>>(bo, nullptr, nullptr, nullptr, out);
}